// round 2
// baseline (speedup 1.0000x reference)
#include <cuda_runtime.h>
#include <cstdint>

#define CAT     160
#define HID     128
#define OUTD    64
#define TILE_E  128
#define THREADS 256
#define KC      32
#define XS_STRIDE 33
#define HS_STRIDE 133

// dynamic smem layout (in floats)
#define HS_OFF   0
#define HS_SIZE  (TILE_E * HS_STRIDE)          // 17024
#define XS_OFF   HS_SIZE
#define XS_SIZE  (TILE_E * XS_STRIDE)          // 4224
#define WS_OFF   (XS_OFF + XS_SIZE)
#define WS_SIZE  (KC * HID)                    // 4096
#define W2S_OFF  XS_OFF                        // stage-2 reuses Xs/Ws region
#define W2S_SIZE (HID * OUTD)                  // 8192
#define SMEM_FLOATS (XS_OFF + (XS_SIZE + WS_SIZE > W2S_SIZE ? XS_SIZE + WS_SIZE : W2S_SIZE))
#define SMEM_BYTES  (SMEM_FLOATS * 4)

__device__ __forceinline__ unsigned long long pack2(float x) {
    unsigned long long r;
    unsigned xi = __float_as_uint(x);
    asm("mov.b64 %0, {%1, %1};" : "=l"(r) : "r"(xi));
    return r;
}

__device__ __forceinline__ void fma2(unsigned long long& d,
                                     unsigned long long a,
                                     unsigned long long b) {
    asm("fma.rn.f32x2 %0, %1, %2, %0;" : "+l"(d) : "l"(a), "l"(b));
}

__device__ __forceinline__ void unpack2(unsigned long long v, float& lo, float& hi) {
    asm("mov.b64 {%0, %1}, %2;" : "=f"(lo), "=f"(hi) : "l"(v));
}

__global__ void __launch_bounds__(THREADS)
edge_mlp_kernel(const float* __restrict__ src,
                const float* __restrict__ dst,
                const float* __restrict__ ea,
                const float* __restrict__ W1,
                const float* __restrict__ b1,
                const float* __restrict__ W2,
                const float* __restrict__ b2,
                float* __restrict__ out,
                int E)
{
    extern __shared__ float sm[];
    float* Hs  = sm + HS_OFF;
    float* Xs  = sm + XS_OFF;
    float* Ws  = sm + WS_OFF;
    float* W2s = sm + W2S_OFF;

    const int tid = threadIdx.x;
    const int e0  = blockIdx.x * TILE_E;

    // ---------------- Stage 1: H = relu(X @ W1 + b1), X = [src|dest|edge] ----
    const int tx = tid & 15, ty = tid >> 4;
    const int r0 = ty * 8,   j0 = tx * 8;

    unsigned long long acc[8][4];
    #pragma unroll
    for (int r = 0; r < 8; r++)
        #pragma unroll
        for (int p = 0; p < 4; p++) acc[r][p] = 0ull;

    for (int ch = 0; ch < 5; ch++) {
        const float* base; int ld, off;
        if (ch < 2)      { base = src; ld = 64; off = ch * 32; }
        else if (ch < 4) { base = dst; ld = 64; off = (ch - 2) * 32; }
        else             { base = ea;  ld = 32; off = 0; }

        // load X chunk [TILE_E x 32]
        #pragma unroll
        for (int i = tid; i < TILE_E * KC; i += THREADS) {
            int r = i >> 5, c = i & 31;
            int e = e0 + r;
            float v = (e < E) ? base[(long)e * ld + off + c] : 0.f;
            Xs[r * XS_STRIDE + c] = v;
        }
        // load W1 chunk [32 x 128]
        const int k0 = ch * KC;
        #pragma unroll
        for (int i = tid; i < KC * HID; i += THREADS) {
            int kk = i >> 7, j = i & 127;
            Ws[kk * HID + j] = W1[(k0 + kk) * HID + j];
        }
        __syncthreads();

        #pragma unroll 8
        for (int kk = 0; kk < KC; kk++) {
            const unsigned long long* wp =
                (const unsigned long long*)(Ws + kk * HID + j0);
            unsigned long long w0 = wp[0], w1 = wp[1], w2 = wp[2], w3 = wp[3];
            #pragma unroll
            for (int r = 0; r < 8; r++) {
                unsigned long long xx = pack2(Xs[(r0 + r) * XS_STRIDE + kk]);
                fma2(acc[r][0], xx, w0);
                fma2(acc[r][1], xx, w1);
                fma2(acc[r][2], xx, w2);
                fma2(acc[r][3], xx, w3);
            }
        }
        __syncthreads();
    }

    // bias + relu -> Hs
    float bj[8];
    #pragma unroll
    for (int jj = 0; jj < 8; jj++) bj[jj] = b1[j0 + jj];
    #pragma unroll
    for (int r = 0; r < 8; r++) {
        #pragma unroll
        for (int p = 0; p < 4; p++) {
            float lo, hi;
            unpack2(acc[r][p], lo, hi);
            lo = fmaxf(lo + bj[2 * p],     0.f);
            hi = fmaxf(hi + bj[2 * p + 1], 0.f);
            Hs[(r0 + r) * HS_STRIDE + j0 + 2 * p]     = lo;
            Hs[(r0 + r) * HS_STRIDE + j0 + 2 * p + 1] = hi;
        }
    }

    // load W2 [128 x 64] into the region previously used by Xs/Ws
    #pragma unroll
    for (int i = tid; i < HID * OUTD; i += THREADS)
        W2s[i] = W2[i];
    __syncthreads();

    // ---------------- Stage 2: out = H @ W2 + b2 -----------------------------
    const int tx2 = tid & 7, ty2 = tid >> 3;
    const int rr0 = ty2 * 4, c0  = tx2 * 8;

    unsigned long long acc2[4][4];
    #pragma unroll
    for (int r = 0; r < 4; r++)
        #pragma unroll
        for (int p = 0; p < 4; p++) acc2[r][p] = 0ull;

    #pragma unroll 8
    for (int k = 0; k < HID; k++) {
        const unsigned long long* wp =
            (const unsigned long long*)(W2s + k * OUTD + c0);
        unsigned long long w0 = wp[0], w1 = wp[1], w2 = wp[2], w3 = wp[3];
        #pragma unroll
        for (int r = 0; r < 4; r++) {
            unsigned long long xx = pack2(Hs[(rr0 + r) * HS_STRIDE + k]);
            fma2(acc2[r][0], xx, w0);
            fma2(acc2[r][1], xx, w1);
            fma2(acc2[r][2], xx, w2);
            fma2(acc2[r][3], xx, w3);
        }
    }

    float bc[8];
    #pragma unroll
    for (int jj = 0; jj < 8; jj++) bc[jj] = b2[c0 + jj];

    #pragma unroll
    for (int r = 0; r < 4; r++) {
        int e = e0 + rr0 + r;
        if (e < E) {
            float v[8];
            #pragma unroll
            for (int p = 0; p < 4; p++) {
                float lo, hi;
                unpack2(acc2[r][p], lo, hi);
                v[2 * p]     = lo + bc[2 * p];
                v[2 * p + 1] = hi + bc[2 * p + 1];
            }
            float4* o = (float4*)(out + (long)e * OUTD + c0);
            o[0] = make_float4(v[0], v[1], v[2], v[3]);
            o[1] = make_float4(v[4], v[5], v[6], v[7]);
        }
    }
}

extern "C" void kernel_launch(void* const* d_in, const int* in_sizes, int n_in,
                              void* d_out, int out_size) {
    const float* src = (const float*)d_in[0];
    const float* dst = (const float*)d_in[1];
    const float* ea  = (const float*)d_in[2];
    // d_in[3] = u, d_in[4] = batch : unused by the reference math
    const float* W1  = (const float*)d_in[5];
    const float* b1  = (const float*)d_in[6];
    const float* W2  = (const float*)d_in[7];
    const float* b2  = (const float*)d_in[8];
    float* out = (float*)d_out;

    const int E = in_sizes[0] / 64;  // src is [E, 64]

    cudaFuncSetAttribute(edge_mlp_kernel,
                         cudaFuncAttributeMaxDynamicSharedMemorySize, SMEM_BYTES);

    const int grid = (E + TILE_E - 1) / TILE_E;
    edge_mlp_kernel<<<grid, THREADS, SMEM_BYTES>>>(src, dst, ea, W1, b1, W2, b2,
                                                   out, E);
}

// round 9
// speedup vs baseline: 1.6661x; 1.6661x over previous
#include <cuda_runtime.h>
#include <cuda_bf16.h>
#include <cstdint>

#define THREADS 256
#define TILE_E  128

// ---- smem byte offsets (dynamic, 16B-aligned base) ------------------------
#define XH_O   0          // X chunk hi  [128][40 bf16]  (80B row stride)
#define XL_O   10240      // X chunk lo
#define WH_O   20480      // W1 chunk hi [128n][40 bf16]
#define WL_O   30720      // W1 chunk lo
#define HH_O   0          // H hi [128][136 bf16] (272B stride)  -- reuses X/W
#define HL_O   34816      // H lo
#define W2H_O  69632      // W2 hi [64n][136 bf16]
#define W2L_O  87040      // W2 lo
#define B1_O   104448     // 128 f32
#define B2_O   104960     // 64 f32
#define OS_O   0          // out stage [128][68 f32] (272B stride) -- reuses H hi
#define SMEM_BYTES 105216

__device__ __forceinline__ uint32_t smem_u32(const void* p) {
    uint32_t a;
    asm("{ .reg .u64 t; cvta.to.shared.u64 t, %1; cvt.u32.u64 %0, t; }" : "=r"(a) : "l"(p));
    return a;
}
// pack {lower 16 = bf16(lo_f), upper 16 = bf16(hi_f)}
__device__ __forceinline__ uint32_t pack_bf16x2(float lo_f, float hi_f) {
    uint32_t r;
    asm("cvt.rn.bf16x2.f32 %0, %1, %2;" : "=r"(r) : "f"(hi_f), "f"(lo_f));
    return r;
}
__device__ __forceinline__ float bf16_round(float x) {
    __nv_bfloat16 h = __float2bfloat16(x);
    return __bfloat162float(h);
}

#define LDSM4(r, addr) \
    asm volatile("ldmatrix.sync.aligned.m8n8.x4.shared.b16 {%0,%1,%2,%3}, [%4];" \
        : "=r"((r)[0]), "=r"((r)[1]), "=r"((r)[2]), "=r"((r)[3]) : "r"(addr))

#define MMA_BF16(c, a, b0, b1) \
    asm volatile("mma.sync.aligned.m16n8k16.row.col.f32.bf16.bf16.f32 " \
        "{%0,%1,%2,%3},{%4,%5,%6,%7},{%8,%9},{%0,%1,%2,%3};" \
        : "+f"((c)[0]), "+f"((c)[1]), "+f"((c)[2]), "+f"((c)[3]) \
        : "r"((a)[0]), "r"((a)[1]), "r"((a)[2]), "r"((a)[3]), "r"(b0), "r"(b1))

// ---- prepacked weight images: bf16 hi/lo, dense --------------------------
// W1: [chunk5][hi/lo][n=128][k=32]   W2: [hi/lo][n=64][k=128]
__device__ __align__(16) unsigned short g_W1[5][2][128][32];
__device__ __align__(16) unsigned short g_W2[2][64][128];

__global__ void prep_kernel(const float* __restrict__ W1, const float* __restrict__ W2) {
    int i = blockIdx.x * blockDim.x + threadIdx.x;
    if (i < 20480) {                       // W1: 5*128*32
        int ch = i >> 12, r = i & 4095, n = r >> 5, kl = r & 31;
        int k = ch * 32 + kl;
        float w = W1[k * 128 + n];
        float h = bf16_round(w);
        g_W1[ch][0][n][kl] = (unsigned short)(pack_bf16x2(h, 0.f) & 0xFFFF);
        g_W1[ch][1][n][kl] = (unsigned short)(pack_bf16x2(w - h, 0.f) & 0xFFFF);
        return;
    }
    int j = i - 20480;
    if (j < 8192) {                        // W2: 64*128
        int n = j >> 7, k = j & 127;
        float w = W2[k * 64 + n];
        float h = bf16_round(w);
        g_W2[0][n][k] = (unsigned short)(pack_bf16x2(h, 0.f) & 0xFFFF);
        g_W2[1][n][k] = (unsigned short)(pack_bf16x2(w - h, 0.f) & 0xFFFF);
    }
}

__global__ void __launch_bounds__(THREADS, 2)
edge_mma(const float* __restrict__ src, const float* __restrict__ dst,
         const float* __restrict__ ea,  const float* __restrict__ b1g,
         const float* __restrict__ b2g, float* __restrict__ out, int E)
{
    extern __shared__ __align__(16) char sm[];
    const uint32_t sb = smem_u32(sm);
    const int tid  = threadIdx.x;
    const int lane = tid & 31;
    const int w    = tid >> 5;
    const int e0   = blockIdx.x * TILE_E;

    const int lrow = lane & 15;
    const uint32_t lsel = ((lane >> 4) & 1) * 16;
    const int gid = lane >> 2, t2 = (lane & 3) * 2;

    // ---- stage W2 images (strided) + biases (once, no deps on X/W region) --
    {
        const uint4* g2 = (const uint4*)g_W2;
        #pragma unroll
        for (int it = 0; it < 8; it++) {
            int i = it * THREADS + tid;            // 2048 uint4 total
            int s = i >> 10, j = i & 1023;
            int n = j >> 4, klb = (j & 15) * 16;   // byte offset in k (8 shorts)
            uint32_t d = (s ? W2L_O : W2H_O) + (uint32_t)n * 272 + klb;
            *(uint4*)(sm + d) = g2[(size_t)s * 1024 + j];
        }
        if (tid < 128) ((float*)(sm + B1_O))[tid] = b1g[tid];
        if (tid < 64)  ((float*)(sm + B2_O))[tid] = b2g[tid];
    }

    // ---- GEMM1: C1[128x128] = X[128x160] @ W1, 5 k-chunks of 32 ------------
    const int m0 = (w & 3) * 32, n0 = (w >> 2) * 64;
    float acc[2][8][4];
    #pragma unroll
    for (int a = 0; a < 2; a++)
        #pragma unroll
        for (int b = 0; b < 8; b++)
            #pragma unroll
            for (int c = 0; c < 4; c++) acc[a][b][c] = 0.f;

    for (int ch = 0; ch < 5; ch++) {
        if (ch) __syncthreads();   // prior chunk's LDSM reads done

        // X chunk: fp32 -> bf16 hi/lo, strided smem
        {
            const float* base; int ld, off;
            if (ch < 2)      { base = src; ld = 64; off = ch * 32; }
            else if (ch < 4) { base = dst; ld = 64; off = (ch - 2) * 32; }
            else             { base = ea;  ld = 32; off = 0; }
            #pragma unroll
            for (int it = 0; it < 4; it++) {
                int i = it * THREADS + tid;        // 1024 float4
                int r = i >> 3, c = (i & 7) * 4;
                int e = e0 + r;
                float4 v = (e < E) ? *(const float4*)(base + (size_t)e * ld + off + c)
                                   : make_float4(0.f, 0.f, 0.f, 0.f);
                float hx = bf16_round(v.x), hy = bf16_round(v.y);
                float hz = bf16_round(v.z), hw = bf16_round(v.w);
                uint2 hi = make_uint2(pack_bf16x2(v.x, v.y), pack_bf16x2(v.z, v.w));
                uint2 lo = make_uint2(pack_bf16x2(v.x - hx, v.y - hy),
                                      pack_bf16x2(v.z - hz, v.w - hw));
                uint32_t d = (uint32_t)r * 80 + (uint32_t)c * 2;
                *(uint2*)(sm + XH_O + d) = hi;
                *(uint2*)(sm + XL_O + d) = lo;
            }
        }
        // W1 chunk images -> strided smem
        {
            const uint4* g1 = (const uint4*)g_W1[ch];
            #pragma unroll
            for (int it = 0; it < 4; it++) {
                int i = it * THREADS + tid;        // 1024 uint4 (512/image)
                int s = i >> 9, j = i & 511;
                int n = j >> 2, klb = (j & 3) * 16;
                uint32_t d = (s ? WL_O : WH_O) + (uint32_t)n * 80 + klb;
                *(uint4*)(sm + d) = g1[(size_t)s * 512 + j];
            }
        }
        __syncthreads();

        #pragma unroll
        for (int ks = 0; ks < 2; ks++) {
            uint32_t ah[2][4], al[2][4];
            #pragma unroll
            for (int ms = 0; ms < 2; ms++) {
                uint32_t ro = (uint32_t)(m0 + ms * 16 + lrow) * 80 + ks * 32 + lsel;
                LDSM4(ah[ms], sb + XH_O + ro);
                LDSM4(al[ms], sb + XL_O + ro);
            }
            #pragma unroll
            for (int nh = 0; nh < 2; nh++) {
                uint32_t bh[8], bl[8];
                uint32_t r0 = (uint32_t)(n0 + nh * 32 + lrow) * 80 + ks * 32 + lsel;
                uint32_t r1 = (uint32_t)(n0 + nh * 32 + 16 + lrow) * 80 + ks * 32 + lsel;
                LDSM4(bh,     sb + WH_O + r0);
                LDSM4(bh + 4, sb + WH_O + r1);
                LDSM4(bl,     sb + WL_O + r0);
                LDSM4(bl + 4, sb + WL_O + r1);
                #pragma unroll
                for (int ms = 0; ms < 2; ms++) {
                    #pragma unroll
                    for (int ns = 0; ns < 4; ns++) {
                        int q = (ns >> 1) * 4, o = ns & 1;
                        uint32_t bh0 = bh[q + o], bh1 = bh[q + o + 2];
                        uint32_t bl0 = bl[q + o], bl1 = bl[q + o + 2];
                        float* c = acc[ms][nh * 4 + ns];
                        MMA_BF16(c, ah[ms], bh0, bh1);
                        MMA_BF16(c, al[ms], bh0, bh1);
                        MMA_BF16(c, ah[ms], bl0, bl1);
                    }
                }
            }
        }
    }
    __syncthreads();   // all GEMM1 reads done; X/W region may be reused as H

    // ---- epilogue1: H = split(relu(C1 + b1)) -> smem ----------------------
    {
        const float* b1s = (const float*)(sm + B1_O);
        #pragma unroll
        for (int ms = 0; ms < 2; ms++) {
            #pragma unroll
            for (int g = 0; g < 8; g++) {
                int row = m0 + ms * 16 + gid;
                int col = n0 + g * 8 + t2;
                const float* c = acc[ms][g];
                float bb0 = b1s[col], bb1 = b1s[col + 1];
                #pragma unroll
                for (int h = 0; h < 2; h++) {
                    int rr = row + h * 8;
                    float v0 = fmaxf(c[2 * h]     + bb0, 0.f);
                    float v1 = fmaxf(c[2 * h + 1] + bb1, 0.f);
                    float h0 = bf16_round(v0), h1 = bf16_round(v1);
                    uint32_t d = (uint32_t)rr * 272 + (uint32_t)col * 2;
                    *(uint32_t*)(sm + HH_O + d) = pack_bf16x2(v0, v1);
                    *(uint32_t*)(sm + HL_O + d) = pack_bf16x2(v0 - h0, v1 - h1);
                }
            }
        }
    }
    __syncthreads();

    // ---- GEMM2: C2[128x64] = H[128x128] @ W2 ------------------------------
    const int n2 = (w >> 2) * 32;
    float acc2[2][4][4];
    #pragma unroll
    for (int a = 0; a < 2; a++)
        #pragma unroll
        for (int b = 0; b < 4; b++)
            #pragma unroll
            for (int c = 0; c < 4; c++) acc2[a][b][c] = 0.f;

    #pragma unroll
    for (int ks = 0; ks < 8; ks++) {
        uint32_t ah[2][4], al[2][4];
        #pragma unroll
        for (int ms = 0; ms < 2; ms++) {
            uint32_t ro = (uint32_t)(m0 + ms * 16 + lrow) * 272 + ks * 32 + lsel;
            LDSM4(ah[ms], sb + HH_O + ro);
            LDSM4(al[ms], sb + HL_O + ro);
        }
        uint32_t bh[8], bl[8];
        uint32_t r0 = (uint32_t)(n2 + lrow) * 272 + ks * 32 + lsel;
        uint32_t r1 = (uint32_t)(n2 + 16 + lrow) * 272 + ks * 32 + lsel;
        LDSM4(bh,     sb + W2H_O + r0);
        LDSM4(bh + 4, sb + W2H_O + r1);
        LDSM4(bl,     sb + W2L_O + r0);
        LDSM4(bl + 4, sb + W2L_O + r1);
        #pragma unroll
        for (int ms = 0; ms < 2; ms++) {
            #pragma unroll
            for (int ns = 0; ns < 4; ns++) {
                int q = (ns >> 1) * 4, o = ns & 1;
                uint32_t bh0 = bh[q + o], bh1 = bh[q + o + 2];
                uint32_t bl0 = bl[q + o], bl1 = bl[q + o + 2];
                float* c = acc2[ms][ns];
                MMA_BF16(c, ah[ms], bh0, bh1);
                MMA_BF16(c, al[ms], bh0, bh1);
                MMA_BF16(c, ah[ms], bl0, bl1);
            }
        }
    }
    __syncthreads();   // all H reads done; H-hi region may be reused as Os

    // ---- epilogue2: out = C2 + b2 (bounce via smem for coalescing) --------
    {
        const float* b2s = (const float*)(sm + B2_O);
        #pragma unroll
        for (int ms = 0; ms < 2; ms++) {
            #pragma unroll
            for (int ns = 0; ns < 4; ns++) {
                int row = m0 + ms * 16 + gid;
                int col = n2 + ns * 8 + t2;
                const float* c = acc2[ms][ns];
                float bb0 = b2s[col], bb1 = b2s[col + 1];
                #pragma unroll
                for (int h = 0; h < 2; h++) {
                    int rr = row + h * 8;
                    float2 v = make_float2(c[2 * h] + bb0, c[2 * h + 1] + bb1);
                    *(float2*)(sm + OS_O + (uint32_t)rr * 272 + (uint32_t)col * 4) = v;
                }
            }
        }
    }
    __syncthreads();
    {
        const char* os = sm + OS_O;
        #pragma unroll
        for (int it = 0; it < 8; it++) {
            int i = it * THREADS + tid;        // 2048 float4
            int r = i >> 4, c = (i & 15) * 4;
            int e = e0 + r;
            if (e < E)
                *(float4*)(out + (size_t)e * 64 + c) =
                    *(const float4*)(os + (uint32_t)r * 272 + (uint32_t)c * 4);
        }
    }
}

extern "C" void kernel_launch(void* const* d_in, const int* in_sizes, int n_in,
                              void* d_out, int out_size) {
    const float* src = (const float*)d_in[0];
    const float* dst = (const float*)d_in[1];
    const float* ea  = (const float*)d_in[2];
    // d_in[3]=u, d_in[4]=batch unused by the reference math
    const float* W1  = (const float*)d_in[5];
    const float* b1  = (const float*)d_in[6];
    const float* W2  = (const float*)d_in[7];
    const float* b2  = (const float*)d_in[8];
    float* out = (float*)d_out;
    const int E = in_sizes[0] / 64;

    cudaFuncSetAttribute(edge_mma, cudaFuncAttributeMaxDynamicSharedMemorySize, SMEM_BYTES);

    prep_kernel<<<112, 256>>>(W1, W2);
    const int grid = (E + TILE_E - 1) / TILE_E;
    edge_mma<<<grid, THREADS, SMEM_BYTES>>>(src, dst, ea, b1, b2, out, E);
}

// round 11
// speedup vs baseline: 3.7385x; 2.2439x over previous
#include <cuda_runtime.h>
#include <cuda_fp16.h>
#include <cstdint>

#define THREADS 256
#define TILE_E  128

// ---- smem byte offsets ----------------------------------------------------
// stage-1 double buffers (X hi/lo + W1 chunk), 80B row stride
#define XH0_O 0
#define XL0_O 10240
#define WB0_O 20480
#define XH1_O 30720
#define XL1_O 40960
#define WB1_O 51200
// H images (272B stride) overlay stage-1 region after GEMM1
#define HH_O  0
#define HL_O  34816
#define W2_O  69632      // 64 x 272B
#define B1_O  87040
#define B2_O  87552
#define OS_O  0          // out stage [128][68 f32], overlays HH after GEMM2
#define SMEM_BYTES 87808

__device__ __forceinline__ uint32_t smem_u32(const void* p) {
    uint32_t a;
    asm("{ .reg .u64 t; cvta.to.shared.u64 t, %1; cvt.u32.u64 %0, t; }" : "=r"(a) : "l"(p));
    return a;
}

#define LDSM4(r, addr) \
    asm volatile("ldmatrix.sync.aligned.m8n8.x4.shared.b16 {%0,%1,%2,%3}, [%4];" \
        : "=r"((r)[0]), "=r"((r)[1]), "=r"((r)[2]), "=r"((r)[3]) : "r"(addr))

#define MMA_F16(c, a, b0, b1) \
    asm volatile("mma.sync.aligned.m16n8k16.row.col.f32.f16.f16.f32 " \
        "{%0,%1,%2,%3},{%4,%5,%6,%7},{%8,%9},{%0,%1,%2,%3};" \
        : "+f"((c)[0]), "+f"((c)[1]), "+f"((c)[2]), "+f"((c)[3]) \
        : "r"((a)[0]), "r"((a)[1]), "r"((a)[2]), "r"((a)[3]), "r"(b0), "r"(b1))

__device__ __forceinline__ uint32_t h2_u32(__half2 h) { return *reinterpret_cast<uint32_t*>(&h); }

// ---- prepacked single-image fp16 weights ----------------------------------
__device__ __align__(16) unsigned short g_W1[5][128][32];  // [chunk][n][k] fp16
__device__ __align__(16) unsigned short g_W2[64][128];     // [n][k] fp16

__global__ void prep_kernel(const float* __restrict__ W1, const float* __restrict__ W2) {
    int i = blockIdx.x * blockDim.x + threadIdx.x;
    if (i < 20480) {                        // 5*128*32
        int ch = i >> 12, r = i & 4095, n = r >> 5, kl = r & 31;
        __half h = __float2half_rn(W1[(ch * 32 + kl) * 128 + n]);
        g_W1[ch][n][kl] = *reinterpret_cast<unsigned short*>(&h);
        return;
    }
    int j = i - 20480;
    if (j < 8192) {                         // 64*128
        int n = j >> 7, k = j & 127;
        __half h = __float2half_rn(W2[k * 64 + n]);
        g_W2[n][k] = *reinterpret_cast<unsigned short*>(&h);
    }
}

// chunk -> (base, ld, off): 0:src[0:32) 1:src[32:64) 2:dst[0:32) 3:dst[32:64) 4:ea[0:32)
__device__ __forceinline__ void chunk_src(int ch, const float*& base, int& ld, int& off,
                                          const float* src, const float* dst, const float* ea) {
    if (ch < 2)      { base = src; ld = 64; off = ch * 32; }
    else if (ch < 4) { base = dst; ld = 64; off = (ch - 2) * 32; }
    else             { base = ea;  ld = 32; off = 0; }
}

__global__ void __launch_bounds__(THREADS, 2)
edge_mma(const float* __restrict__ src, const float* __restrict__ dst,
         const float* __restrict__ ea,  const float* __restrict__ b1g,
         const float* __restrict__ b2g, float* __restrict__ out, int E)
{
    extern __shared__ __align__(16) char sm[];
    const uint32_t sb = smem_u32(sm);
    const int tid  = threadIdx.x;
    const int lane = tid & 31;
    const int w    = tid >> 5;
    const int e0   = blockIdx.x * TILE_E;

    const int lrow = lane & 15;
    const uint32_t lsel = ((lane >> 4) & 1) * 16;
    const int gid = lane >> 2, t2 = (lane & 3) * 2;
    const int m0 = (w & 3) * 32, n0 = (w >> 2) * 64;

    // ---- stage W2 (strided) + biases --------------------------------------
    {
        const uint4* g2 = (const uint4*)g_W2;   // 1024 uint4
        #pragma unroll
        for (int it = 0; it < 4; it++) {
            int i = it * THREADS + tid;
            int n = i >> 4, klb = (i & 15) * 16;
            *(uint4*)(sm + W2_O + (uint32_t)n * 272 + klb) = g2[i];
        }
        if (tid < 128) ((float*)(sm + B1_O))[tid] = b1g[tid];
        if (tid < 64)  ((float*)(sm + B2_O))[tid] = b2g[tid];
    }

    float acc[2][8][4];
    #pragma unroll
    for (int a = 0; a < 2; a++)
        #pragma unroll
        for (int b = 0; b < 8; b++)
            #pragma unroll
            for (int c = 0; c < 4; c++) acc[a][b][c] = 0.f;

    float4 xr[4];
    uint4  wr[2];

    // ---- helpers as lambdas ------------------------------------------------
    auto load_chunk = [&](int ch) {
        const float* base; int ld, off;
        chunk_src(ch, base, ld, off, src, dst, ea);
        #pragma unroll
        for (int it = 0; it < 4; it++) {
            int i = it * THREADS + tid;
            int r = i >> 3, c = (i & 7) * 4;
            int e = e0 + r;
            xr[it] = (e < E) ? *(const float4*)(base + (size_t)e * ld + off + c)
                             : make_float4(0.f, 0.f, 0.f, 0.f);
        }
        const uint4* gw = (const uint4*)g_W1[ch];   // 512 uint4
        #pragma unroll
        for (int it = 0; it < 2; it++) wr[it] = gw[it * THREADS + tid];
    };
    auto store_chunk = [&](int bs) {
        uint32_t xh_o = bs ? XH1_O : XH0_O;
        uint32_t xl_o = bs ? XL1_O : XL0_O;
        uint32_t wb_o = bs ? WB1_O : WB0_O;
        #pragma unroll
        for (int it = 0; it < 4; it++) {
            int i = it * THREADS + tid;
            int r = i >> 3, c = (i & 7) * 4;
            float4 v = xr[it];
            __half2 h01 = __floats2half2_rn(v.x, v.y);
            __half2 h23 = __floats2half2_rn(v.z, v.w);
            float2 f01 = __half22float2(h01), f23 = __half22float2(h23);
            __half2 l01 = __floats2half2_rn(v.x - f01.x, v.y - f01.y);
            __half2 l23 = __floats2half2_rn(v.z - f23.x, v.w - f23.y);
            uint32_t d = (uint32_t)r * 80 + (uint32_t)c * 2;
            *(uint2*)(sm + xh_o + d) = make_uint2(h2_u32(h01), h2_u32(h23));
            *(uint2*)(sm + xl_o + d) = make_uint2(h2_u32(l01), h2_u32(l23));
        }
        #pragma unroll
        for (int it = 0; it < 2; it++) {
            int i = it * THREADS + tid;
            int n = i >> 2, klb = (i & 3) * 16;
            *(uint4*)(sm + wb_o + (uint32_t)n * 80 + klb) = wr[it];
        }
    };
    auto mma_chunk = [&](int bs) {
        uint32_t xh_o = bs ? XH1_O : XH0_O;
        uint32_t xl_o = bs ? XL1_O : XL0_O;
        uint32_t wb_o = bs ? WB1_O : WB0_O;
        #pragma unroll
        for (int ks = 0; ks < 2; ks++) {
            uint32_t ah[2][4], al[2][4];
            #pragma unroll
            for (int ms = 0; ms < 2; ms++) {
                uint32_t ro = (uint32_t)(m0 + ms * 16 + lrow) * 80 + ks * 32 + lsel;
                LDSM4(ah[ms], sb + xh_o + ro);
                LDSM4(al[ms], sb + xl_o + ro);
            }
            #pragma unroll
            for (int nh = 0; nh < 2; nh++) {
                uint32_t bh[8];
                uint32_t r0 = (uint32_t)(n0 + nh * 32 + lrow) * 80 + ks * 32 + lsel;
                uint32_t r1 = (uint32_t)(n0 + nh * 32 + 16 + lrow) * 80 + ks * 32 + lsel;
                LDSM4(bh,     sb + wb_o + r0);
                LDSM4(bh + 4, sb + wb_o + r1);
                #pragma unroll
                for (int ms = 0; ms < 2; ms++) {
                    #pragma unroll
                    for (int ns = 0; ns < 4; ns++) {
                        int q = (ns >> 1) * 4, o = ns & 1;
                        uint32_t b0 = bh[q + o], b1 = bh[q + o + 2];
                        float* c = acc[ms][nh * 4 + ns];
                        MMA_F16(c, ah[ms], b0, b1);
                        MMA_F16(c, al[ms], b0, b1);
                    }
                }
            }
        }
    };

    // ---- GEMM1 pipeline: prefetch chunk i+1 regs, MMA chunk i, store i+1 ---
    load_chunk(0);
    store_chunk(0);
    __syncthreads();
    #pragma unroll
    for (int ch = 0; ch < 5; ch++) {
        if (ch < 4) load_chunk(ch + 1);      // LDGs in flight under MMAs
        mma_chunk(ch & 1);
        if (ch < 4) store_chunk((ch + 1) & 1);
        __syncthreads();
    }

    // ---- epilogue1: H = fp16split(relu(C1 + b1)) -> smem -------------------
    {
        const float* b1s = (const float*)(sm + B1_O);
        #pragma unroll
        for (int ms = 0; ms < 2; ms++) {
            #pragma unroll
            for (int g = 0; g < 8; g++) {
                int row = m0 + ms * 16 + gid;
                int col = n0 + g * 8 + t2;
                const float* c = acc[ms][g];
                float bb0 = b1s[col], bb1 = b1s[col + 1];
                #pragma unroll
                for (int h = 0; h < 2; h++) {
                    int rr = row + h * 8;
                    float v0 = fmaxf(c[2 * h]     + bb0, 0.f);
                    float v1 = fmaxf(c[2 * h + 1] + bb1, 0.f);
                    __half2 hh = __floats2half2_rn(v0, v1);
                    float2 f = __half22float2(hh);
                    __half2 ll = __floats2half2_rn(v0 - f.x, v1 - f.y);
                    uint32_t d = (uint32_t)rr * 272 + (uint32_t)col * 2;
                    *(uint32_t*)(sm + HH_O + d) = h2_u32(hh);
                    *(uint32_t*)(sm + HL_O + d) = h2_u32(ll);
                }
            }
        }
    }
    __syncthreads();

    // ---- GEMM2: C2[128x64] = H[128x128] @ W2 (2 passes) --------------------
    const int n2 = (w >> 2) * 32;
    float acc2[2][4][4];
    #pragma unroll
    for (int a = 0; a < 2; a++)
        #pragma unroll
        for (int b = 0; b < 4; b++)
            #pragma unroll
            for (int c = 0; c < 4; c++) acc2[a][b][c] = 0.f;

    #pragma unroll
    for (int ks = 0; ks < 8; ks++) {
        uint32_t ah[2][4], al[2][4];
        #pragma unroll
        for (int ms = 0; ms < 2; ms++) {
            uint32_t ro = (uint32_t)(m0 + ms * 16 + lrow) * 272 + ks * 32 + lsel;
            LDSM4(ah[ms], sb + HH_O + ro);
            LDSM4(al[ms], sb + HL_O + ro);
        }
        uint32_t bh[8];
        uint32_t r0 = (uint32_t)(n2 + lrow) * 272 + ks * 32 + lsel;
        uint32_t r1 = (uint32_t)(n2 + 16 + lrow) * 272 + ks * 32 + lsel;
        LDSM4(bh,     sb + W2_O + r0);
        LDSM4(bh + 4, sb + W2_O + r1);
        #pragma unroll
        for (int ms = 0; ms < 2; ms++) {
            #pragma unroll
            for (int ns = 0; ns < 4; ns++) {
                int q = (ns >> 1) * 4, o = ns & 1;
                uint32_t b0 = bh[q + o], b1 = bh[q + o + 2];
                float* c = acc2[ms][ns];
                MMA_F16(c, ah[ms], b0, b1);
                MMA_F16(c, al[ms], b0, b1);
            }
        }
    }
    __syncthreads();   // H reads done; OS overlays HH

    // ---- epilogue2: out = C2 + b2 (smem bounce for coalesced stores) -------
    {
        const float* b2s = (const float*)(sm + B2_O);
        #pragma unroll
        for (int ms = 0; ms < 2; ms++) {
            #pragma unroll
            for (int ns = 0; ns < 4; ns++) {
                int row = m0 + ms * 16 + gid;
                int col = n2 + ns * 8 + t2;
                const float* c = acc2[ms][ns];
                float bb0 = b2s[col], bb1 = b2s[col + 1];
                #pragma unroll
                for (int h = 0; h < 2; h++) {
                    int rr = row + h * 8;
                    float2 v = make_float2(c[2 * h] + bb0, c[2 * h + 1] + bb1);
                    *(float2*)(sm + OS_O + (uint32_t)rr * 272 + (uint32_t)col * 4) = v;
                }
            }
        }
    }
    __syncthreads();
    {
        const char* os = sm + OS_O;
        #pragma unroll
        for (int it = 0; it < 8; it++) {
            int i = it * THREADS + tid;
            int r = i >> 4, c = (i & 15) * 4;
            int e = e0 + r;
            if (e < E)
                *(float4*)(out + (size_t)e * 64 + c) =
                    *(const float4*)(os + (uint32_t)r * 272 + (uint32_t)c * 4);
        }
    }
}

extern "C" void kernel_launch(void* const* d_in, const int* in_sizes, int n_in,
                              void* d_out, int out_size) {
    const float* src = (const float*)d_in[0];
    const float* dst = (const float*)d_in[1];
    const float* ea  = (const float*)d_in[2];
    // d_in[3]=u, d_in[4]=batch unused by the reference math
    const float* W1  = (const float*)d_in[5];
    const float* b1  = (const float*)d_in[6];
    const float* W2  = (const float*)d_in[7];
    const float* b2  = (const float*)d_in[8];
    float* out = (float*)d_out;
    const int E = in_sizes[0] / 64;

    cudaFuncSetAttribute(edge_mma, cudaFuncAttributeMaxDynamicSharedMemorySize, SMEM_BYTES);

    prep_kernel<<<112, 256>>>(W1, W2);
    const int grid = (E + TILE_E - 1) / TILE_E;
    edge_mma<<<grid, THREADS, SMEM_BYTES>>>(src, dst, ea, b1, b2, out, E);
}

// round 13
// speedup vs baseline: 3.7660x; 1.0074x over previous
#include <cuda_runtime.h>
#include <cuda_fp16.h>
#include <cstdint>

#define THREADS 256
#define TILE_E  128

// ---- smem byte offsets ----------------------------------------------------
// stage-1 double buffers (X hi/lo + W1 chunk), 80B row stride
#define XH0_O 0
#define XL0_O 10240
#define WB0_O 20480
#define XH1_O 30720
#define XL1_O 40960
#define WB1_O 51200
#define W2_O  61440      // 64 rows x 272B
#define B1_O  78848      // 128 f32
#define B2_O  79360      // 64 f32
#define SMEM_BYTES 79616

__device__ __forceinline__ uint32_t smem_u32(const void* p) {
    uint32_t a;
    asm("{ .reg .u64 t; cvta.to.shared.u64 t, %1; cvt.u32.u64 %0, t; }" : "=r"(a) : "l"(p));
    return a;
}

#define LDSM4(r, addr) \
    asm volatile("ldmatrix.sync.aligned.m8n8.x4.shared.b16 {%0,%1,%2,%3}, [%4];" \
        : "=r"((r)[0]), "=r"((r)[1]), "=r"((r)[2]), "=r"((r)[3]) : "r"(addr))

#define MMA_F16(c, a, b0, b1) \
    asm volatile("mma.sync.aligned.m16n8k16.row.col.f32.f16.f16.f32 " \
        "{%0,%1,%2,%3},{%4,%5,%6,%7},{%8,%9},{%0,%1,%2,%3};" \
        : "+f"((c)[0]), "+f"((c)[1]), "+f"((c)[2]), "+f"((c)[3]) \
        : "r"((a)[0]), "r"((a)[1]), "r"((a)[2]), "r"((a)[3]), "r"(b0), "r"(b1))

__device__ __forceinline__ uint32_t h2_u32(__half2 h) { return *reinterpret_cast<uint32_t*>(&h); }

// ---- prepacked single-image fp16 weights ----------------------------------
__device__ __align__(16) unsigned short g_W1[5][128][32];  // [chunk][n][k] fp16
__device__ __align__(16) unsigned short g_W2[64][128];     // [n][k] fp16

__global__ void prep_kernel(const float* __restrict__ W1, const float* __restrict__ W2) {
    int i = blockIdx.x * blockDim.x + threadIdx.x;
    if (i < 20480) {                        // 5*128*32
        int ch = i >> 12, r = i & 4095, n = r >> 5, kl = r & 31;
        __half h = __float2half_rn(W1[(ch * 32 + kl) * 128 + n]);
        g_W1[ch][n][kl] = *reinterpret_cast<unsigned short*>(&h);
        return;
    }
    int j = i - 20480;
    if (j < 8192) {                         // 64*128
        int n = j >> 7, k = j & 127;
        __half h = __float2half_rn(W2[k * 64 + n]);
        g_W2[n][k] = *reinterpret_cast<unsigned short*>(&h);
    }
}

// chunk -> (base, ld, off): 0:src[0:32) 1:src[32:64) 2:dst[0:32) 3:dst[32:64) 4:ea[0:32)
__device__ __forceinline__ void chunk_src(int ch, const float*& base, int& ld, int& off,
                                          const float* src, const float* dst, const float* ea) {
    if (ch < 2)      { base = src; ld = 64; off = ch * 32; }
    else if (ch < 4) { base = dst; ld = 64; off = (ch - 2) * 32; }
    else             { base = ea;  ld = 32; off = 0; }
}

__global__ void __launch_bounds__(THREADS, 2)
edge_mma(const float* __restrict__ src, const float* __restrict__ dst,
         const float* __restrict__ ea,  const float* __restrict__ b1g,
         const float* __restrict__ b2g, float* __restrict__ out, int E)
{
    extern __shared__ __align__(16) char sm[];
    const uint32_t sb = smem_u32(sm);
    const int tid  = threadIdx.x;
    const int lane = tid & 31;
    const int w    = tid >> 5;
    const int e0   = blockIdx.x * TILE_E;

    const int lrow = lane & 15;
    const uint32_t lsel = ((lane >> 4) & 1) * 16;
    const int gid = lane >> 2, t2 = (lane & 3) * 2;
    const int m0 = w * 16;                  // warp tile: m16 x n128

    // ---- stage W2 (strided) + biases --------------------------------------
    {
        const uint4* g2 = (const uint4*)g_W2;   // 1024 uint4
        #pragma unroll
        for (int it = 0; it < 4; it++) {
            int i = it * THREADS + tid;
            int n = i >> 4, klb = (i & 15) * 16;
            *(uint4*)(sm + W2_O + (uint32_t)n * 272 + klb) = g2[i];
        }
        if (tid < 128) ((float*)(sm + B1_O))[tid] = b1g[tid];
        if (tid < 64)  ((float*)(sm + B2_O))[tid] = b2g[tid];
    }

    float acc[16][4];
    #pragma unroll
    for (int g = 0; g < 16; g++)
        #pragma unroll
        for (int c = 0; c < 4; c++) acc[g][c] = 0.f;

    float4 xr[4];
    uint4  wr[2];

    auto load_chunk = [&](int ch) {
        const float* base; int ld, off;
        chunk_src(ch, base, ld, off, src, dst, ea);
        #pragma unroll
        for (int it = 0; it < 4; it++) {
            int i = it * THREADS + tid;
            int r = i >> 3, c = (i & 7) * 4;
            int e = e0 + r;
            xr[it] = (e < E) ? *(const float4*)(base + (size_t)e * ld + off + c)
                             : make_float4(0.f, 0.f, 0.f, 0.f);
        }
        const uint4* gw = (const uint4*)g_W1[ch];   // 512 uint4
        #pragma unroll
        for (int it = 0; it < 2; it++) wr[it] = gw[it * THREADS + tid];
    };
    auto store_chunk = [&](int bs) {
        uint32_t xh_o = bs ? XH1_O : XH0_O;
        uint32_t xl_o = bs ? XL1_O : XL0_O;
        uint32_t wb_o = bs ? WB1_O : WB0_O;
        #pragma unroll
        for (int it = 0; it < 4; it++) {
            int i = it * THREADS + tid;
            int r = i >> 3, c = (i & 7) * 4;
            float4 v = xr[it];
            __half2 h01 = __floats2half2_rn(v.x, v.y);
            __half2 h23 = __floats2half2_rn(v.z, v.w);
            float2 f01 = __half22float2(h01), f23 = __half22float2(h23);
            __half2 l01 = __floats2half2_rn(v.x - f01.x, v.y - f01.y);
            __half2 l23 = __floats2half2_rn(v.z - f23.x, v.w - f23.y);
            uint32_t d = (uint32_t)r * 80 + (uint32_t)c * 2;
            *(uint2*)(sm + xh_o + d) = make_uint2(h2_u32(h01), h2_u32(h23));
            *(uint2*)(sm + xl_o + d) = make_uint2(h2_u32(l01), h2_u32(l23));
        }
        #pragma unroll
        for (int it = 0; it < 2; it++) {
            int i = it * THREADS + tid;
            int n = i >> 2, klb = (i & 3) * 16;
            *(uint4*)(sm + wb_o + (uint32_t)n * 80 + klb) = wr[it];
        }
    };
    auto mma_chunk = [&](int bs) {
        uint32_t xh_o = bs ? XH1_O : XH0_O;
        uint32_t xl_o = bs ? XL1_O : XL0_O;
        uint32_t wb_o = bs ? WB1_O : WB0_O;
        #pragma unroll
        for (int ks = 0; ks < 2; ks++) {
            uint32_t ah[4], al[4];
            uint32_t ro = (uint32_t)(m0 + lrow) * 80 + ks * 32 + lsel;
            LDSM4(ah, sb + xh_o + ro);
            LDSM4(al, sb + xl_o + ro);
            #pragma unroll
            for (int nh = 0; nh < 4; nh++) {
                uint32_t bh[8];
                uint32_t r0 = (uint32_t)(nh * 32 + lrow) * 80 + ks * 32 + lsel;
                uint32_t r1 = (uint32_t)(nh * 32 + 16 + lrow) * 80 + ks * 32 + lsel;
                LDSM4(bh,     sb + wb_o + r0);
                LDSM4(bh + 4, sb + wb_o + r1);
                #pragma unroll
                for (int ns = 0; ns < 4; ns++) {
                    int q = (ns >> 1) * 4, o = ns & 1;
                    uint32_t b0 = bh[q + o], b1 = bh[q + o + 2];
                    float* c = acc[nh * 4 + ns];
                    MMA_F16(c, ah, b0, b1);
                    MMA_F16(c, al, b0, b1);
                }
            }
        }
    };

    // ---- GEMM1 pipeline: prefetch chunk i+1 regs, MMA chunk i, store i+1 ---
    load_chunk(0);
    store_chunk(0);
    __syncthreads();
    #pragma unroll
    for (int ch = 0; ch < 5; ch++) {
        if (ch < 4) load_chunk(ch + 1);      // LDGs in flight under MMAs
        mma_chunk(ch & 1);
        if (ch < 4) { store_chunk((ch + 1) & 1); __syncthreads(); }
    }

    // ---- epilogue1 IN REGISTERS: A2 = fp16split(relu(C1 + b1)) -------------
    // C-fragment (row gid/gid+8, cols t2,t2+1 of group g) == A-fragment
    // (a0..a3) of k-group kg=g>>1 for GEMM2. No smem round-trip.
    uint32_t a2h[8][4], a2l[8][4];
    {
        const float* b1s = (const float*)(sm + B1_O);
        #pragma unroll
        for (int g = 0; g < 16; g++) {
            float bb0 = b1s[g * 8 + t2], bb1 = b1s[g * 8 + t2 + 1];
            float v0 = fmaxf(acc[g][0] + bb0, 0.f);
            float v1 = fmaxf(acc[g][1] + bb1, 0.f);
            float v2 = fmaxf(acc[g][2] + bb0, 0.f);
            float v3 = fmaxf(acc[g][3] + bb1, 0.f);
            __half2 h01 = __floats2half2_rn(v0, v1);
            __half2 h23 = __floats2half2_rn(v2, v3);
            float2 f01 = __half22float2(h01), f23 = __half22float2(h23);
            __half2 l01 = __floats2half2_rn(v0 - f01.x, v1 - f01.y);
            __half2 l23 = __floats2half2_rn(v2 - f23.x, v3 - f23.y);
            int kg = g >> 1, s = (g & 1) * 2;
            a2h[kg][s]     = h2_u32(h01);
            a2h[kg][s + 1] = h2_u32(h23);
            a2l[kg][s]     = h2_u32(l01);
            a2l[kg][s + 1] = h2_u32(l23);
        }
    }

    // ---- GEMM2: C2[16x64] per warp = A2 @ W2 (sync-free) -------------------
    float acc2[8][4];
    #pragma unroll
    for (int g = 0; g < 8; g++)
        #pragma unroll
        for (int c = 0; c < 4; c++) acc2[g][c] = 0.f;

    #pragma unroll
    for (int kg = 0; kg < 8; kg++) {
        uint32_t bh[16];
        #pragma unroll
        for (int nb = 0; nb < 4; nb++) {
            uint32_t ro = (uint32_t)(nb * 16 + lrow) * 272 + kg * 32 + lsel;
            LDSM4(bh + nb * 4, sb + W2_O + ro);
        }
        #pragma unroll
        for (int ns = 0; ns < 8; ns++) {
            int base = (ns >> 1) * 4, o = ns & 1;
            uint32_t b0 = bh[base + o], b1 = bh[base + o + 2];
            float* c = acc2[ns];
            MMA_F16(c, a2h[kg], b0, b1);
            MMA_F16(c, a2l[kg], b0, b1);
        }
    }

    // ---- epilogue2: direct float2 stores (one 32B sector per STG.64) -------
    {
        const float* b2s = (const float*)(sm + B2_O);
        int e_lo = e0 + m0 + gid;
        #pragma unroll
        for (int ns = 0; ns < 8; ns++) {
            int col = ns * 8 + t2;
            float bb0 = b2s[col], bb1 = b2s[col + 1];
            const float* c = acc2[ns];
            if (e_lo < E)
                *(float2*)(out + (size_t)e_lo * 64 + col) =
                    make_float2(c[0] + bb0, c[1] + bb1);
            if (e_lo + 8 < E)
                *(float2*)(out + (size_t)(e_lo + 8) * 64 + col) =
                    make_float2(c[2] + bb0, c[3] + bb1);
        }
    }
}

extern "C" void kernel_launch(void* const* d_in, const int* in_sizes, int n_in,
                              void* d_out, int out_size) {
    const float* src = (const float*)d_in[0];
    const float* dst = (const float*)d_in[1];
    const float* ea  = (const float*)d_in[2];
    // d_in[3]=u, d_in[4]=batch unused by the reference math
    const float* W1  = (const float*)d_in[5];
    const float* b1  = (const float*)d_in[6];
    const float* W2  = (const float*)d_in[7];
    const float* b2  = (const float*)d_in[8];
    float* out = (float*)d_out;
    const int E = in_sizes[0] / 64;

    cudaFuncSetAttribute(edge_mma, cudaFuncAttributeMaxDynamicSharedMemorySize, SMEM_BYTES);

    prep_kernel<<<112, 256>>>(W1, W2);
    const int grid = (E + TILE_E - 1) / TILE_E;
    edge_mma<<<grid, THREADS, SMEM_BYTES>>>(src, dst, ea, b1, b2, out, E);
}

// round 14
// speedup vs baseline: 5.5172x; 1.4650x over previous
#include <cuda_runtime.h>
#include <cuda_fp16.h>
#include <cstdint>

#define THREADS 256
#define TILE_E  128

// ---- smem byte offsets ----------------------------------------------------
#define XB0_O 0          // X chunk fp16 [128][40] (80B stride), double buffered
#define XB1_O 10240
#define W1_O  20480      // 5 chunks x [128n][40k] fp16, 80B stride (10240 each)
#define W2_O  71680      // 64 rows x 272B
#define B1_O  89088      // 128 f32
#define B2_O  89600      // 64 f32
#define SMEM_BYTES 89856

__device__ __forceinline__ uint32_t smem_u32(const void* p) {
    uint32_t a;
    asm("{ .reg .u64 t; cvta.to.shared.u64 t, %1; cvt.u32.u64 %0, t; }" : "=r"(a) : "l"(p));
    return a;
}

#define LDSM4(r, addr) \
    asm volatile("ldmatrix.sync.aligned.m8n8.x4.shared.b16 {%0,%1,%2,%3}, [%4];" \
        : "=r"((r)[0]), "=r"((r)[1]), "=r"((r)[2]), "=r"((r)[3]) : "r"(addr))

#define MMA_F16(c, a, b0, b1) \
    asm volatile("mma.sync.aligned.m16n8k16.row.col.f32.f16.f16.f32 " \
        "{%0,%1,%2,%3},{%4,%5,%6,%7},{%8,%9},{%0,%1,%2,%3};" \
        : "+f"((c)[0]), "+f"((c)[1]), "+f"((c)[2]), "+f"((c)[3]) \
        : "r"((a)[0]), "r"((a)[1]), "r"((a)[2]), "r"((a)[3]), "r"(b0), "r"(b1))

__device__ __forceinline__ uint32_t h2_u32(__half2 h) { return *reinterpret_cast<uint32_t*>(&h); }

// ---- prepacked fp16 weights ------------------------------------------------
__device__ __align__(16) unsigned short g_W1[5][128][32];  // [chunk][n][k]
__device__ __align__(16) unsigned short g_W2[64][128];     // [n][k]

__global__ void prep_kernel(const float* __restrict__ W1, const float* __restrict__ W2) {
    int i = blockIdx.x * blockDim.x + threadIdx.x;
    if (i < 20480) {
        int ch = i >> 12, r = i & 4095, n = r >> 5, kl = r & 31;
        __half h = __float2half_rn(W1[(ch * 32 + kl) * 128 + n]);
        g_W1[ch][n][kl] = *reinterpret_cast<unsigned short*>(&h);
        return;
    }
    int j = i - 20480;
    if (j < 8192) {
        int n = j >> 7, k = j & 127;
        __half h = __float2half_rn(W2[k * 64 + n]);
        g_W2[n][k] = *reinterpret_cast<unsigned short*>(&h);
    }
}

// chunk -> (base, ld, off): 0:src[0:32) 1:src[32:64) 2:dst[0:32) 3:dst[32:64) 4:ea
__device__ __forceinline__ void chunk_src(int ch, const float*& base, int& ld, int& off,
                                          const float* src, const float* dst, const float* ea) {
    if (ch < 2)      { base = src; ld = 64; off = ch * 32; }
    else if (ch < 4) { base = dst; ld = 64; off = (ch - 2) * 32; }
    else             { base = ea;  ld = 32; off = 0; }
}

__global__ void __launch_bounds__(THREADS, 2)
edge_mma(const float* __restrict__ src, const float* __restrict__ dst,
         const float* __restrict__ ea,  const float* __restrict__ b1g,
         const float* __restrict__ b2g, float* __restrict__ out, int E)
{
    extern __shared__ __align__(16) char sm[];
    const uint32_t sb = smem_u32(sm);
    const int tid  = threadIdx.x;
    const int lane = tid & 31;
    const int w    = tid >> 5;
    const int e0   = blockIdx.x * TILE_E;

    const int lrow = lane & 15;
    const uint32_t lsel = ((lane >> 4) & 1) * 16;
    const int gid = lane >> 2, t2 = (lane & 3) * 2;
    const int m0 = w * 16;                  // warp tile: m16 x n128

    // ---- one-time staging: all W1 chunks, W2, biases ----------------------
    {
        const uint4* g1 = (const uint4*)g_W1;      // 2560 uint4
        #pragma unroll
        for (int it = 0; it < 10; it++) {
            int i = it * THREADS + tid;
            int ch = i >> 9, j = i & 511;
            int n = j >> 2, klb = (j & 3) * 16;
            *(uint4*)(sm + W1_O + (uint32_t)ch * 10240 + (uint32_t)n * 80 + klb) = g1[i];
        }
        const uint4* g2 = (const uint4*)g_W2;      // 1024 uint4
        #pragma unroll
        for (int it = 0; it < 4; it++) {
            int i = it * THREADS + tid;
            int n = i >> 4, klb = (i & 15) * 16;
            *(uint4*)(sm + W2_O + (uint32_t)n * 272 + klb) = g2[i];
        }
        if (tid < 128) ((float*)(sm + B1_O))[tid] = b1g[tid];
        if (tid < 64)  ((float*)(sm + B2_O))[tid] = b2g[tid];
    }

    float acc[16][4];
    #pragma unroll
    for (int g = 0; g < 16; g++)
        #pragma unroll
        for (int c = 0; c < 4; c++) acc[g][c] = 0.f;

    float4 xr[4];

    auto load_x = [&](int ch) {
        const float* base; int ld, off;
        chunk_src(ch, base, ld, off, src, dst, ea);
        #pragma unroll
        for (int it = 0; it < 4; it++) {
            int i = it * THREADS + tid;
            int r = i >> 3, c = (i & 7) * 4;
            int e = e0 + r;
            xr[it] = (e < E) ? *(const float4*)(base + (size_t)e * ld + off + c)
                             : make_float4(0.f, 0.f, 0.f, 0.f);
        }
    };
    auto store_x = [&](int bs) {
        uint32_t xb_o = bs ? XB1_O : XB0_O;
        #pragma unroll
        for (int it = 0; it < 4; it++) {
            int i = it * THREADS + tid;
            int r = i >> 3, c = (i & 7) * 4;
            float4 v = xr[it];
            __half2 h01 = __floats2half2_rn(v.x, v.y);
            __half2 h23 = __floats2half2_rn(v.z, v.w);
            uint32_t d = (uint32_t)r * 80 + (uint32_t)c * 2;
            *(uint2*)(sm + xb_o + d) = make_uint2(h2_u32(h01), h2_u32(h23));
        }
    };
    auto mma_chunk = [&](int bs, int ch) {
        uint32_t xb_o = bs ? XB1_O : XB0_O;
        uint32_t wb_o = W1_O + (uint32_t)ch * 10240;
        #pragma unroll
        for (int ks = 0; ks < 2; ks++) {
            uint32_t ah[4];
            uint32_t ro = (uint32_t)(m0 + lrow) * 80 + ks * 32 + lsel;
            LDSM4(ah, sb + xb_o + ro);
            #pragma unroll
            for (int nh = 0; nh < 4; nh++) {
                uint32_t bh[8];
                uint32_t r0 = (uint32_t)(nh * 32 + lrow) * 80 + ks * 32 + lsel;
                uint32_t r1 = (uint32_t)(nh * 32 + 16 + lrow) * 80 + ks * 32 + lsel;
                LDSM4(bh,     sb + wb_o + r0);
                LDSM4(bh + 4, sb + wb_o + r1);
                #pragma unroll
                for (int ns = 0; ns < 4; ns++) {
                    int q = (ns >> 1) * 4, o = ns & 1;
                    MMA_F16(acc[nh * 4 + ns], ah, bh[q + o], bh[q + o + 2]);
                }
            }
        }
    };

    // ---- GEMM1 pipeline: prefetch chunk i+1 regs, MMA chunk i --------------
    load_x(0);
    store_x(0);
    __syncthreads();
    #pragma unroll
    for (int ch = 0; ch < 5; ch++) {
        if (ch < 4) load_x(ch + 1);          // LDGs in flight under MMAs
        mma_chunk(ch & 1, ch);
        if (ch < 4) { store_x((ch + 1) & 1); __syncthreads(); }
    }

    // ---- epilogue1 IN REGISTERS: A2 = fp16(relu(C1 + b1)) ------------------
    // C-fragment of group g == A-fragment of k-group g>>1 for GEMM2.
    uint32_t a2h[8][4];
    {
        const float* b1s = (const float*)(sm + B1_O);
        #pragma unroll
        for (int g = 0; g < 16; g++) {
            float bb0 = b1s[g * 8 + t2], bb1 = b1s[g * 8 + t2 + 1];
            float v0 = fmaxf(acc[g][0] + bb0, 0.f);
            float v1 = fmaxf(acc[g][1] + bb1, 0.f);
            float v2 = fmaxf(acc[g][2] + bb0, 0.f);
            float v3 = fmaxf(acc[g][3] + bb1, 0.f);
            int kg = g >> 1, s = (g & 1) * 2;
            a2h[kg][s]     = h2_u32(__floats2half2_rn(v0, v1));
            a2h[kg][s + 1] = h2_u32(__floats2half2_rn(v2, v3));
        }
    }

    // ---- GEMM2: C2[16x64] per warp = A2 @ W2 (sync-free, single pass) ------
    float acc2[8][4];
    #pragma unroll
    for (int g = 0; g < 8; g++)
        #pragma unroll
        for (int c = 0; c < 4; c++) acc2[g][c] = 0.f;

    #pragma unroll
    for (int kg = 0; kg < 8; kg++) {
        uint32_t bh[16];
        #pragma unroll
        for (int nb = 0; nb < 4; nb++) {
            uint32_t ro = (uint32_t)(nb * 16 + lrow) * 272 + kg * 32 + lsel;
            LDSM4(bh + nb * 4, sb + W2_O + ro);
        }
        #pragma unroll
        for (int ns = 0; ns < 8; ns++) {
            int base = (ns >> 1) * 4, o = ns & 1;
            MMA_F16(acc2[ns], a2h[kg], bh[base + o], bh[base + o + 2]);
        }
    }

    // ---- epilogue2: direct float2 stores (one 32B sector per STG.64) -------
    {
        const float* b2s = (const float*)(sm + B2_O);
        int e_lo = e0 + m0 + gid;
        #pragma unroll
        for (int ns = 0; ns < 8; ns++) {
            int col = ns * 8 + t2;
            float bb0 = b2s[col], bb1 = b2s[col + 1];
            const float* c = acc2[ns];
            if (e_lo < E)
                *(float2*)(out + (size_t)e_lo * 64 + col) =
                    make_float2(c[0] + bb0, c[1] + bb1);
            if (e_lo + 8 < E)
                *(float2*)(out + (size_t)(e_lo + 8) * 64 + col) =
                    make_float2(c[2] + bb0, c[3] + bb1);
        }
    }
}

extern "C" void kernel_launch(void* const* d_in, const int* in_sizes, int n_in,
                              void* d_out, int out_size) {
    const float* src = (const float*)d_in[0];
    const float* dst = (const float*)d_in[1];
    const float* ea  = (const float*)d_in[2];
    // d_in[3]=u, d_in[4]=batch unused by the reference math
    const float* W1  = (const float*)d_in[5];
    const float* b1  = (const float*)d_in[6];
    const float* W2  = (const float*)d_in[7];
    const float* b2  = (const float*)d_in[8];
    float* out = (float*)d_out;
    const int E = in_sizes[0] / 64;

    cudaFuncSetAttribute(edge_mma, cudaFuncAttributeMaxDynamicSharedMemorySize, SMEM_BYTES);

    prep_kernel<<<112, 256>>>(W1, W2);
    const int grid = (E + TILE_E - 1) / TILE_E;
    edge_mma<<<grid, THREADS, SMEM_BYTES>>>(src, dst, ea, b1, b2, out, E);
}

// round 15
// speedup vs baseline: 6.7914x; 1.2309x over previous
#include <cuda_runtime.h>
#include <cuda_fp16.h>
#include <cstdint>

#define THREADS 256
#define TILE_E  128
#define GRID_P  304     // 2 CTAs x 152 SMs (GB300)

// ---- smem byte offsets ----------------------------------------------------
#define XB0_O 0          // X chunk fp16 [128][40] (80B stride), double buffered
#define XB1_O 10240
#define W1_O  20480      // 5 chunks x [128n][40k] fp16, 80B stride (10240 each)
#define W2_O  71680      // 64 rows x 272B
#define B1_O  89088      // 128 f32
#define B2_O  89600      // 64 f32
#define SMEM_BYTES 89856

__device__ __forceinline__ uint32_t smem_u32(const void* p) {
    uint32_t a;
    asm("{ .reg .u64 t; cvta.to.shared.u64 t, %1; cvt.u32.u64 %0, t; }" : "=r"(a) : "l"(p));
    return a;
}

#define LDSM4(r, addr) \
    asm volatile("ldmatrix.sync.aligned.m8n8.x4.shared.b16 {%0,%1,%2,%3}, [%4];" \
        : "=r"((r)[0]), "=r"((r)[1]), "=r"((r)[2]), "=r"((r)[3]) : "r"(addr))

#define MMA_F16(c, a, b0, b1) \
    asm volatile("mma.sync.aligned.m16n8k16.row.col.f32.f16.f16.f32 " \
        "{%0,%1,%2,%3},{%4,%5,%6,%7},{%8,%9},{%0,%1,%2,%3};" \
        : "+f"((c)[0]), "+f"((c)[1]), "+f"((c)[2]), "+f"((c)[3]) \
        : "r"((a)[0]), "r"((a)[1]), "r"((a)[2]), "r"((a)[3]), "r"(b0), "r"(b1))

__device__ __forceinline__ uint32_t h2_u32(__half2 h) { return *reinterpret_cast<uint32_t*>(&h); }

// ---- prepacked fp16 weights ------------------------------------------------
__device__ __align__(16) unsigned short g_W1[5][128][32];  // [chunk][n][k]
__device__ __align__(16) unsigned short g_W2[64][128];     // [n][k]

__global__ void prep_kernel(const float* __restrict__ W1, const float* __restrict__ W2) {
    int i = blockIdx.x * blockDim.x + threadIdx.x;
    if (i < 20480) {
        int ch = i >> 12, r = i & 4095, n = r >> 5, kl = r & 31;
        __half h = __float2half_rn(W1[(ch * 32 + kl) * 128 + n]);
        g_W1[ch][n][kl] = *reinterpret_cast<unsigned short*>(&h);
        return;
    }
    int j = i - 20480;
    if (j < 8192) {
        int n = j >> 7, k = j & 127;
        __half h = __float2half_rn(W2[k * 64 + n]);
        g_W2[n][k] = *reinterpret_cast<unsigned short*>(&h);
    }
}

// chunk -> (base, ld, off): 0:src[0:32) 1:src[32:64) 2:dst[0:32) 3:dst[32:64) 4:ea
__device__ __forceinline__ void chunk_src(int ch, const float*& base, int& ld, int& off,
                                          const float* src, const float* dst, const float* ea) {
    if (ch < 2)      { base = src; ld = 64; off = ch * 32; }
    else if (ch < 4) { base = dst; ld = 64; off = (ch - 2) * 32; }
    else             { base = ea;  ld = 32; off = 0; }
}

__global__ void __launch_bounds__(THREADS, 2)
edge_mma(const float* __restrict__ src, const float* __restrict__ dst,
         const float* __restrict__ ea,  const float* __restrict__ b1g,
         const float* __restrict__ b2g, float* __restrict__ out,
         int E, int ntiles)
{
    extern __shared__ __align__(16) char sm[];
    const uint32_t sb = smem_u32(sm);
    const int tid  = threadIdx.x;
    const int lane = tid & 31;
    const int w    = tid >> 5;

    const int lrow = lane & 15;
    const uint32_t lsel = ((lane >> 4) & 1) * 16;
    const int gid = lane >> 2, t2 = (lane & 3) * 2;
    const int m0 = w * 16;                  // warp tile: m16 x n128

    // ---- one-time staging: all W1 chunks, W2, biases ----------------------
    {
        const uint4* g1 = (const uint4*)g_W1;      // 2560 uint4
        #pragma unroll
        for (int it = 0; it < 10; it++) {
            int i = it * THREADS + tid;
            int ch = i >> 9, j = i & 511;
            int n = j >> 2, klb = (j & 3) * 16;
            *(uint4*)(sm + W1_O + (uint32_t)ch * 10240 + (uint32_t)n * 80 + klb) = g1[i];
        }
        const uint4* g2 = (const uint4*)g_W2;      // 1024 uint4
        #pragma unroll
        for (int it = 0; it < 4; it++) {
            int i = it * THREADS + tid;
            int n = i >> 4, klb = (i & 15) * 16;
            *(uint4*)(sm + W2_O + (uint32_t)n * 272 + klb) = g2[i];
        }
        if (tid < 128) ((float*)(sm + B1_O))[tid] = b1g[tid];
        if (tid < 64)  ((float*)(sm + B2_O))[tid] = b2g[tid];
    }
    __syncthreads();

    float4 xr[4];

    auto load_x = [&](int e0, int ch) {
        const float* base; int ld, off;
        chunk_src(ch, base, ld, off, src, dst, ea);
        #pragma unroll
        for (int it = 0; it < 4; it++) {
            int i = it * THREADS + tid;
            int r = i >> 3, c = (i & 7) * 4;
            int e = e0 + r;
            xr[it] = (e < E) ? *(const float4*)(base + (size_t)e * ld + off + c)
                             : make_float4(0.f, 0.f, 0.f, 0.f);
        }
    };
    auto store_x = [&](int bs) {
        uint32_t xb_o = bs ? XB1_O : XB0_O;
        #pragma unroll
        for (int it = 0; it < 4; it++) {
            int i = it * THREADS + tid;
            int r = i >> 3, c = (i & 7) * 4;
            float4 v = xr[it];
            __half2 h01 = __floats2half2_rn(v.x, v.y);
            __half2 h23 = __floats2half2_rn(v.z, v.w);
            uint32_t d = (uint32_t)r * 80 + (uint32_t)c * 2;
            *(uint2*)(sm + xb_o + d) = make_uint2(h2_u32(h01), h2_u32(h23));
        }
    };

    // ---- persistent tile loop ---------------------------------------------
    int tile = blockIdx.x;
    if (tile < ntiles) load_x(tile * TILE_E, 0);   // preamble prefetch

    for (; tile < ntiles; tile += GRID_P) {
        const int e0 = tile * TILE_E;

        float acc[16][4];
        #pragma unroll
        for (int g = 0; g < 16; g++)
            #pragma unroll
            for (int c = 0; c < 4; c++) acc[g][c] = 0.f;

        store_x(0);
        __syncthreads();

        #pragma unroll
        for (int ch = 0; ch < 5; ch++) {
            // prefetch: next chunk of this tile, or chunk0 of the next tile
            if (ch < 4) {
                load_x(e0, ch + 1);
            } else {
                int nt = tile + GRID_P;
                if (nt < ntiles) load_x(nt * TILE_E, 0);
            }
            // MMA on chunk ch (buffer ch&1)
            {
                uint32_t xb_o = (ch & 1) ? XB1_O : XB0_O;
                uint32_t wb_o = W1_O + (uint32_t)ch * 10240;
                #pragma unroll
                for (int ks = 0; ks < 2; ks++) {
                    uint32_t ah[4];
                    uint32_t ro = (uint32_t)(m0 + lrow) * 80 + ks * 32 + lsel;
                    LDSM4(ah, sb + xb_o + ro);
                    #pragma unroll
                    for (int nh = 0; nh < 4; nh++) {
                        uint32_t bh[8];
                        uint32_t r0 = (uint32_t)(nh * 32 + lrow) * 80 + ks * 32 + lsel;
                        uint32_t r1 = (uint32_t)(nh * 32 + 16 + lrow) * 80 + ks * 32 + lsel;
                        LDSM4(bh,     sb + wb_o + r0);
                        LDSM4(bh + 4, sb + wb_o + r1);
                        #pragma unroll
                        for (int ns = 0; ns < 4; ns++) {
                            int q = (ns >> 1) * 4, o = ns & 1;
                            MMA_F16(acc[nh * 4 + ns], ah, bh[q + o], bh[q + o + 2]);
                        }
                    }
                }
            }
            if (ch < 4) { store_x((ch + 1) & 1); __syncthreads(); }
        }

        // ---- epilogue1 IN REGISTERS: A2 = fp16(relu(C1 + b1)) --------------
        uint32_t a2h[8][4];
        {
            const float* b1s = (const float*)(sm + B1_O);
            #pragma unroll
            for (int g = 0; g < 16; g++) {
                float bb0 = b1s[g * 8 + t2], bb1 = b1s[g * 8 + t2 + 1];
                float v0 = fmaxf(acc[g][0] + bb0, 0.f);
                float v1 = fmaxf(acc[g][1] + bb1, 0.f);
                float v2 = fmaxf(acc[g][2] + bb0, 0.f);
                float v3 = fmaxf(acc[g][3] + bb1, 0.f);
                int kg = g >> 1, s = (g & 1) * 2;
                a2h[kg][s]     = h2_u32(__floats2half2_rn(v0, v1));
                a2h[kg][s + 1] = h2_u32(__floats2half2_rn(v2, v3));
            }
        }

        // ---- GEMM2: C2[16x64] per warp = A2 @ W2 (sync-free) ---------------
        float acc2[8][4];
        #pragma unroll
        for (int g = 0; g < 8; g++)
            #pragma unroll
            for (int c = 0; c < 4; c++) acc2[g][c] = 0.f;

        #pragma unroll
        for (int kg = 0; kg < 8; kg++) {
            uint32_t bh[16];
            #pragma unroll
            for (int nb = 0; nb < 4; nb++) {
                uint32_t ro = (uint32_t)(nb * 16 + lrow) * 272 + kg * 32 + lsel;
                LDSM4(bh + nb * 4, sb + W2_O + ro);
            }
            #pragma unroll
            for (int ns = 0; ns < 8; ns++) {
                int base = (ns >> 1) * 4, o = ns & 1;
                MMA_F16(acc2[ns], a2h[kg], bh[base + o], bh[base + o + 2]);
            }
        }

        // ---- epilogue2: direct float2 stores -------------------------------
        {
            const float* b2s = (const float*)(sm + B2_O);
            int e_lo = e0 + m0 + gid;
            #pragma unroll
            for (int ns = 0; ns < 8; ns++) {
                int col = ns * 8 + t2;
                float bb0 = b2s[col], bb1 = b2s[col + 1];
                const float* c = acc2[ns];
                if (e_lo < E)
                    *(float2*)(out + (size_t)e_lo * 64 + col) =
                        make_float2(c[0] + bb0, c[1] + bb1);
                if (e_lo + 8 < E)
                    *(float2*)(out + (size_t)(e_lo + 8) * 64 + col) =
                        make_float2(c[2] + bb0, c[3] + bb1);
            }
        }
        __syncthreads();   // protect X buffer 0 before next tile's store_x(0)
    }
}

extern "C" void kernel_launch(void* const* d_in, const int* in_sizes, int n_in,
                              void* d_out, int out_size) {
    const float* src = (const float*)d_in[0];
    const float* dst = (const float*)d_in[1];
    const float* ea  = (const float*)d_in[2];
    // d_in[3]=u, d_in[4]=batch unused by the reference math
    const float* W1  = (const float*)d_in[5];
    const float* b1  = (const float*)d_in[6];
    const float* W2  = (const float*)d_in[7];
    const float* b2  = (const float*)d_in[8];
    float* out = (float*)d_out;
    const int E = in_sizes[0] / 64;
    const int ntiles = (E + TILE_E - 1) / TILE_E;

    cudaFuncSetAttribute(edge_mma, cudaFuncAttributeMaxDynamicSharedMemorySize, SMEM_BYTES);

    prep_kernel<<<112, 256>>>(W1, W2);
    const int grid = ntiles < GRID_P ? ntiles : GRID_P;
    edge_mma<<<grid, THREADS, SMEM_BYTES>>>(src, dst, ea, b1, b2, out, E, ntiles);
}